// round 3
// baseline (speedup 1.0000x reference)
#include <cuda_runtime.h>
#include <math.h>

#define BB 32
#define TT 256
#define VV 4096
#define NROWS (BB * TT)

#define NCHUNK 2
#define BATCH_PER_CHUNK (BB / NCHUNK)              // 16
#define ROWS_PER_CHUNK (BATCH_PER_CHUNK * TT)      // 4096

__device__ float g_rowC[NROWS];  // m + logZ per row
__device__ float g_ent[NROWS];   // entropy per row
__device__ float g_g[NROWS];     // final per-row scale

// ---------------------------------------------------------------------------
// Stats: 2 rows per block (256 thr). 8 front-batched LDG.128 per thread for
// high MLP; shared barriers across the two rows' reductions.
// ---------------------------------------------------------------------------
__global__ __launch_bounds__(256) void rowstats2_kernel(const float* __restrict__ logits,
                                                        int rowbase) {
    const int pr  = blockIdx.x;                 // row pair within chunk
    const int tid = threadIdx.x;
    const float4* in0 = (const float4*)(logits + (size_t)(2 * pr)     * VV);
    const float4* in1 = (const float4*)(logits + (size_t)(2 * pr + 1) * VV);

    float4 a[4], b[4];
#pragma unroll
    for (int i = 0; i < 4; i++) a[i] = in0[tid + 256 * i];
#pragma unroll
    for (int i = 0; i < 4; i++) b[i] = in1[tid + 256 * i];

    float m0 = -1e30f, m1 = -1e30f;
#pragma unroll
    for (int i = 0; i < 4; i++) {
        m0 = fmaxf(m0, fmaxf(fmaxf(a[i].x, a[i].y), fmaxf(a[i].z, a[i].w)));
        m1 = fmaxf(m1, fmaxf(fmaxf(b[i].x, b[i].y), fmaxf(b[i].z, b[i].w)));
    }

    __shared__ float redm0[8], redm1[8];
    __shared__ float redZ0[8], redZ1[8];
    __shared__ float redS0[8], redS1[8];

#pragma unroll
    for (int o = 16; o > 0; o >>= 1) {
        m0 = fmaxf(m0, __shfl_xor_sync(0xffffffffu, m0, o));
        m1 = fmaxf(m1, __shfl_xor_sync(0xffffffffu, m1, o));
    }
    if ((tid & 31) == 0) { redm0[tid >> 5] = m0; redm1[tid >> 5] = m1; }
    __syncthreads();
    {
        float t0 = redm0[0], t1 = redm1[0];
#pragma unroll
        for (int i = 1; i < 8; i++) { t0 = fmaxf(t0, redm0[i]); t1 = fmaxf(t1, redm1[i]); }
        m0 = t0; m1 = t1;
    }

    float Z0 = 0.f, S0 = 0.f, Z1 = 0.f, S1 = 0.f;
#pragma unroll
    for (int i = 0; i < 4; i++) {
        float xa[4] = {a[i].x, a[i].y, a[i].z, a[i].w};
        float xb[4] = {b[i].x, b[i].y, b[i].z, b[i].w};
#pragma unroll
        for (int j = 0; j < 4; j++) {
            float d0 = xa[j] - m0;
            float e0 = __expf(d0);
            Z0 += e0; S0 = fmaf(e0, d0, S0);
            float d1 = xb[j] - m1;
            float e1 = __expf(d1);
            Z1 += e1; S1 = fmaf(e1, d1, S1);
        }
    }
#pragma unroll
    for (int o = 16; o > 0; o >>= 1) {
        Z0 += __shfl_xor_sync(0xffffffffu, Z0, o);
        S0 += __shfl_xor_sync(0xffffffffu, S0, o);
        Z1 += __shfl_xor_sync(0xffffffffu, Z1, o);
        S1 += __shfl_xor_sync(0xffffffffu, S1, o);
    }
    if ((tid & 31) == 0) {
        redZ0[tid >> 5] = Z0; redS0[tid >> 5] = S0;
        redZ1[tid >> 5] = Z1; redS1[tid >> 5] = S1;
    }
    __syncthreads();

    if (tid < 2) {
        const float* rZ = (tid == 0) ? redZ0 : redZ1;
        const float* rS = (tid == 0) ? redS0 : redS1;
        float mm = (tid == 0) ? m0 : m1;
        float Zt = 0.f, St = 0.f;
#pragma unroll
        for (int i = 0; i < 8; i++) { Zt += rZ[i]; St += rS[i]; }
        float logZ = logf(Zt);
        int row = rowbase + 2 * pr + tid;
        g_rowC[row] = mm + logZ;
        g_ent[row]  = logZ - St / Zt;
    }
}

// ---------------------------------------------------------------------------
// Flags: tiny MLP + sigmoid + sequential cumprod. One block per batch.
// ---------------------------------------------------------------------------
__global__ __launch_bounds__(256) void flags_kernel(const float* __restrict__ w1,
                                                    const float* __restrict__ b1,
                                                    const float* __restrict__ w2,
                                                    const float* __restrict__ b2,
                                                    int batchbase) {
    const int b = batchbase + blockIdx.x;
    const int t = threadIdx.x;

    __shared__ float sw1[128], sb1[128], sw2[128];
    __shared__ float sflag[TT];  // sflag[t] = flags[t+1]

    if (t < 128) { sw1[t] = w1[t]; sb1[t] = b1[t]; sw2[t] = w2[t]; }
    __syncthreads();

    float f = 1.0f;  // flags[T] = 1
    if (t < TT - 1) {
        float e = g_ent[b * TT + t];
        const float entropy_max = logf((float)TT);
        float norm = 2.0f * e / entropy_max - 1.0f;
        float lin = 0.f;
#pragma unroll 8
        for (int j = 0; j < 128; j++) {
            float h = fmaxf(fmaf(norm, sw1[j], sb1[j]), 0.f);
            lin = fmaf(h, sw2[j], lin);
        }
        lin = 2.0f * lin + b2[0];
        float ns = (float)(TT - 1 - t);
        float zarg = lin - logf(ns);
        f = 1.0f / (1.0f + expf(-zarg));
    }
    sflag[t] = f;
    __syncthreads();

    if (t == 0) {
        float res = 1.0f;
        for (int s = 0; s < TT; s++) {
            g_g[b * TT + s] = sflag[s] * res;
            res *= (1.0f - sflag[s]);
        }
    }
}

// ---------------------------------------------------------------------------
// Scale: 2 rows per block, reverse order within the chunk (rows the stats
// pass touched last are hottest in L2). Evict-first reads, streaming stores.
// ---------------------------------------------------------------------------
__global__ __launch_bounds__(256) void scale2_kernel(const float* __restrict__ logits,
                                                     float* __restrict__ out,
                                                     int rowbase) {
    const int pr  = gridDim.x - 1 - blockIdx.x;   // reverse pair order
    const int tid = threadIdx.x;
    const int r0 = 2 * pr, r1 = 2 * pr + 1;
    const float c0 = g_rowC[rowbase + r0];
    const float c1 = g_rowC[rowbase + r1];
    const float s0 = g_g[rowbase + r0];
    const float s1 = g_g[rowbase + r1];
    const float4* in0 = (const float4*)(logits + (size_t)r0 * VV);
    const float4* in1 = (const float4*)(logits + (size_t)r1 * VV);
    float4* o0 = (float4*)(out + (size_t)r0 * VV);
    float4* o1 = (float4*)(out + (size_t)r1 * VV);

    float4 a[4], b[4];
#pragma unroll
    for (int i = 0; i < 4; i++) a[i] = __ldcs(&in0[tid + 256 * i]);
#pragma unroll
    for (int i = 0; i < 4; i++) b[i] = __ldcs(&in1[tid + 256 * i]);

#pragma unroll
    for (int i = 0; i < 4; i++) {
        float4 r;
        r.x = __expf(a[i].x - c0) * s0;
        r.y = __expf(a[i].y - c0) * s0;
        r.z = __expf(a[i].z - c0) * s0;
        r.w = __expf(a[i].w - c0) * s0;
        __stcs(&o0[tid + 256 * i], r);
    }
#pragma unroll
    for (int i = 0; i < 4; i++) {
        float4 r;
        r.x = __expf(b[i].x - c1) * s1;
        r.y = __expf(b[i].y - c1) * s1;
        r.z = __expf(b[i].z - c1) * s1;
        r.w = __expf(b[i].w - c1) * s1;
        __stcs(&o1[tid + 256 * i], r);
    }
}

// ---------------------------------------------------------------------------
extern "C" void kernel_launch(void* const* d_in, const int* in_sizes, int n_in,
                              void* d_out, int out_size) {
    const float* logits = (const float*)d_in[0];
    const float* w1     = (const float*)d_in[1];
    const float* b1     = (const float*)d_in[2];
    const float* w2     = (const float*)d_in[3];
    const float* b2     = (const float*)d_in[4];
    float* out          = (float*)d_out;

    for (int c = 0; c < NCHUNK; c++) {
        const int rowbase = c * ROWS_PER_CHUNK;
        const float* lc = logits + (size_t)rowbase * VV;
        float* oc       = out    + (size_t)rowbase * VV;
        rowstats2_kernel<<<ROWS_PER_CHUNK / 2, 256>>>(lc, rowbase);
        flags_kernel<<<BATCH_PER_CHUNK, 256>>>(w1, b1, w2, b2, c * BATCH_PER_CHUNK);
        scale2_kernel<<<ROWS_PER_CHUNK / 2, 256>>>(lc, oc, rowbase);
    }
}

// round 4
// speedup vs baseline: 1.0005x; 1.0005x over previous
#include <cuda_runtime.h>
#include <math.h>

#define BB 32
#define TT 256
#define VV 4096
#define NROWS (BB * TT)

#define NCHUNK 2
#define BATCH_PER_CHUNK (BB / NCHUNK)              // 16
#define ROWS_PER_CHUNK (BATCH_PER_CHUNK * TT)      // 4096

__device__ float g_rowC[NROWS];  // m + logZ per row
__device__ float g_ent[NROWS];   // entropy per row
__device__ float g_g[NROWS];     // final per-row scale

// ---------------------------------------------------------------------------
// Stats: 2 rows per block (256 thr). 8 front-batched LDG.128 per thread for
// high MLP; shared barriers across the two rows' reductions.
// ---------------------------------------------------------------------------
__global__ __launch_bounds__(256) void rowstats2_kernel(const float* __restrict__ logits,
                                                        int rowbase) {
    const int pr  = blockIdx.x;                 // row pair within chunk
    const int tid = threadIdx.x;
    const float4* in0 = (const float4*)(logits + (size_t)(2 * pr)     * VV);
    const float4* in1 = (const float4*)(logits + (size_t)(2 * pr + 1) * VV);

    float4 a[4], b[4];
#pragma unroll
    for (int i = 0; i < 4; i++) a[i] = in0[tid + 256 * i];
#pragma unroll
    for (int i = 0; i < 4; i++) b[i] = in1[tid + 256 * i];

    float m0 = -1e30f, m1 = -1e30f;
#pragma unroll
    for (int i = 0; i < 4; i++) {
        m0 = fmaxf(m0, fmaxf(fmaxf(a[i].x, a[i].y), fmaxf(a[i].z, a[i].w)));
        m1 = fmaxf(m1, fmaxf(fmaxf(b[i].x, b[i].y), fmaxf(b[i].z, b[i].w)));
    }

    __shared__ float redm0[8], redm1[8];
    __shared__ float redZ0[8], redZ1[8];
    __shared__ float redS0[8], redS1[8];

#pragma unroll
    for (int o = 16; o > 0; o >>= 1) {
        m0 = fmaxf(m0, __shfl_xor_sync(0xffffffffu, m0, o));
        m1 = fmaxf(m1, __shfl_xor_sync(0xffffffffu, m1, o));
    }
    if ((tid & 31) == 0) { redm0[tid >> 5] = m0; redm1[tid >> 5] = m1; }
    __syncthreads();
    {
        float t0 = redm0[0], t1 = redm1[0];
#pragma unroll
        for (int i = 1; i < 8; i++) { t0 = fmaxf(t0, redm0[i]); t1 = fmaxf(t1, redm1[i]); }
        m0 = t0; m1 = t1;
    }

    float Z0 = 0.f, S0 = 0.f, Z1 = 0.f, S1 = 0.f;
#pragma unroll
    for (int i = 0; i < 4; i++) {
        float xa[4] = {a[i].x, a[i].y, a[i].z, a[i].w};
        float xb[4] = {b[i].x, b[i].y, b[i].z, b[i].w};
#pragma unroll
        for (int j = 0; j < 4; j++) {
            float d0 = xa[j] - m0;
            float e0 = __expf(d0);
            Z0 += e0; S0 = fmaf(e0, d0, S0);
            float d1 = xb[j] - m1;
            float e1 = __expf(d1);
            Z1 += e1; S1 = fmaf(e1, d1, S1);
        }
    }
#pragma unroll
    for (int o = 16; o > 0; o >>= 1) {
        Z0 += __shfl_xor_sync(0xffffffffu, Z0, o);
        S0 += __shfl_xor_sync(0xffffffffu, S0, o);
        Z1 += __shfl_xor_sync(0xffffffffu, Z1, o);
        S1 += __shfl_xor_sync(0xffffffffu, S1, o);
    }
    if ((tid & 31) == 0) {
        redZ0[tid >> 5] = Z0; redS0[tid >> 5] = S0;
        redZ1[tid >> 5] = Z1; redS1[tid >> 5] = S1;
    }
    __syncthreads();

    if (tid < 2) {
        const float* rZ = (tid == 0) ? redZ0 : redZ1;
        const float* rS = (tid == 0) ? redS0 : redS1;
        float mm = (tid == 0) ? m0 : m1;
        float Zt = 0.f, St = 0.f;
#pragma unroll
        for (int i = 0; i < 8; i++) { Zt += rZ[i]; St += rS[i]; }
        float logZ = logf(Zt);
        int row = rowbase + 2 * pr + tid;
        g_rowC[row] = mm + logZ;
        g_ent[row]  = logZ - St / Zt;
    }
}

// ---------------------------------------------------------------------------
// Flags: tiny MLP + sigmoid + sequential cumprod. One block per batch.
// ---------------------------------------------------------------------------
__global__ __launch_bounds__(256) void flags_kernel(const float* __restrict__ w1,
                                                    const float* __restrict__ b1,
                                                    const float* __restrict__ w2,
                                                    const float* __restrict__ b2,
                                                    int batchbase) {
    const int b = batchbase + blockIdx.x;
    const int t = threadIdx.x;

    __shared__ float sw1[128], sb1[128], sw2[128];
    __shared__ float sflag[TT];  // sflag[t] = flags[t+1]

    if (t < 128) { sw1[t] = w1[t]; sb1[t] = b1[t]; sw2[t] = w2[t]; }
    __syncthreads();

    float f = 1.0f;  // flags[T] = 1
    if (t < TT - 1) {
        float e = g_ent[b * TT + t];
        const float entropy_max = logf((float)TT);
        float norm = 2.0f * e / entropy_max - 1.0f;
        float lin = 0.f;
#pragma unroll 8
        for (int j = 0; j < 128; j++) {
            float h = fmaxf(fmaf(norm, sw1[j], sb1[j]), 0.f);
            lin = fmaf(h, sw2[j], lin);
        }
        lin = 2.0f * lin + b2[0];
        float ns = (float)(TT - 1 - t);
        float zarg = lin - logf(ns);
        f = 1.0f / (1.0f + expf(-zarg));
    }
    sflag[t] = f;
    __syncthreads();

    if (t == 0) {
        float res = 1.0f;
        for (int s = 0; s < TT; s++) {
            g_g[b * TT + s] = sflag[s] * res;
            res *= (1.0f - sflag[s]);
        }
    }
}

// ---------------------------------------------------------------------------
// Scale: 2 rows per block, reverse order within the chunk (rows the stats
// pass touched last are hottest in L2). Evict-first reads, streaming stores.
// ---------------------------------------------------------------------------
__global__ __launch_bounds__(256) void scale2_kernel(const float* __restrict__ logits,
                                                     float* __restrict__ out,
                                                     int rowbase) {
    const int pr  = gridDim.x - 1 - blockIdx.x;   // reverse pair order
    const int tid = threadIdx.x;
    const int r0 = 2 * pr, r1 = 2 * pr + 1;
    const float c0 = g_rowC[rowbase + r0];
    const float c1 = g_rowC[rowbase + r1];
    const float s0 = g_g[rowbase + r0];
    const float s1 = g_g[rowbase + r1];
    const float4* in0 = (const float4*)(logits + (size_t)r0 * VV);
    const float4* in1 = (const float4*)(logits + (size_t)r1 * VV);
    float4* o0 = (float4*)(out + (size_t)r0 * VV);
    float4* o1 = (float4*)(out + (size_t)r1 * VV);

    float4 a[4], b[4];
#pragma unroll
    for (int i = 0; i < 4; i++) a[i] = __ldcs(&in0[tid + 256 * i]);
#pragma unroll
    for (int i = 0; i < 4; i++) b[i] = __ldcs(&in1[tid + 256 * i]);

#pragma unroll
    for (int i = 0; i < 4; i++) {
        float4 r;
        r.x = __expf(a[i].x - c0) * s0;
        r.y = __expf(a[i].y - c0) * s0;
        r.z = __expf(a[i].z - c0) * s0;
        r.w = __expf(a[i].w - c0) * s0;
        __stcs(&o0[tid + 256 * i], r);
    }
#pragma unroll
    for (int i = 0; i < 4; i++) {
        float4 r;
        r.x = __expf(b[i].x - c1) * s1;
        r.y = __expf(b[i].y - c1) * s1;
        r.z = __expf(b[i].z - c1) * s1;
        r.w = __expf(b[i].w - c1) * s1;
        __stcs(&o1[tid + 256 * i], r);
    }
}

// ---------------------------------------------------------------------------
extern "C" void kernel_launch(void* const* d_in, const int* in_sizes, int n_in,
                              void* d_out, int out_size) {
    const float* logits = (const float*)d_in[0];
    const float* w1     = (const float*)d_in[1];
    const float* b1     = (const float*)d_in[2];
    const float* w2     = (const float*)d_in[3];
    const float* b2     = (const float*)d_in[4];
    float* out          = (float*)d_out;

    for (int c = 0; c < NCHUNK; c++) {
        const int rowbase = c * ROWS_PER_CHUNK;
        const float* lc = logits + (size_t)rowbase * VV;
        float* oc       = out    + (size_t)rowbase * VV;
        rowstats2_kernel<<<ROWS_PER_CHUNK / 2, 256>>>(lc, rowbase);
        flags_kernel<<<BATCH_PER_CHUNK, 256>>>(w1, b1, w2, b2, c * BATCH_PER_CHUNK);
        scale2_kernel<<<ROWS_PER_CHUNK / 2, 256>>>(lc, oc, rowbase);
    }
}